// round 17
// baseline (speedup 1.0000x reference)
#include <cuda_runtime.h>
#include <cuda_bf16.h>

#define KBINS 16
#define MAGIC 8388608.0f   // 2^23
#define VPT 8              // float4s per thread per tile
#define TPB 256
#define TILE4 (VPT * TPB)  // 2048 float4s = 32KB per tile

// Branchless LCQ quantize-dequantize. Per element:
//   f   = min(|x| * (16/alpha), 15.9999990)    // in [0,16); ~16 <=> high region
//   bi  = lowbits(fadd_rd(f, 2^23)) & 15       // == floor(f), bit-exact
//   y15 = fma(tab[bi].x, f, tab[bi].y)         // tab = {gx, s*beta - gx*bi}
//   q   = lowbits(fadd_rn(y15, 2^23)) & 15     // == rint(y15), bit-exact
//   out = copysign(lutA[q], x)                 // lutA[15] = alpha (high region)
//
// PERSISTENT grid: 740 CTAs (5/SM), each owns a contiguous run of ~5-6 tiles.
// Lane-parallel setup (shuffle reductions/scan) runs once per CTA slot
// instead of once per tile -> the mid-kernel CTA-start bubbles that R16
// identified as the binding overhead are gone entirely.

__device__ __forceinline__ float lcq_elem(float xx, float c,
                                          const float2* __restrict__ tab,
                                          const float* __restrict__ lutA) {
    float f = fminf(fabsf(xx) * c, 15.9999990f);
    int bi = __float_as_int(__fadd_rd(f, MAGIC)) & 15;   // floor(f)
    float2 gd = tab[bi];                                 // {gx, d}
    float y15 = fmaf(gd.x, f, gd.y);
    int q = __float_as_int(__fadd_rn(y15, MAGIC)) & 15;  // rint(y15)
    return copysignf(lutA[q], xx);
}

__device__ __forceinline__ void lcq_vec4(float4& v, float c,
                                         const float2* __restrict__ tab,
                                         const float* __restrict__ lutA) {
    v.x = lcq_elem(v.x, c, tab, lutA);
    v.y = lcq_elem(v.y, c, tab, lutA);
    v.z = lcq_elem(v.z, c, tab, lutA);
    v.w = lcq_elem(v.w, c, tab, lutA);
}

__global__ void __launch_bounds__(TPB, 5)
lcq_kernel(const float* __restrict__ x,
           const float* __restrict__ thr,
           const float* __restrict__ theta,
           const float* __restrict__ dst,
           const int* __restrict__ qp,
           float* __restrict__ out,
           int ntiles,   // number of complete 32KB tiles
           int n4,       // total float4 count
           int n) {      // total element count
    __shared__ float2 s_tab[KBINS];    // {gx, s*beta - gx*bi}
    __shared__ float  s_lutA[KBINS];   // alpha * expand(q/s)
    __shared__ float  s_c;             // 16/alpha

    // ---- lane-parallel setup on warp 0 (runs once per persistent CTA) ----
    if (threadIdx.x < 32) {
        const int lane = threadIdx.x;
        const unsigned FULL = 0xFFFFFFFFu;

        float th = (lane < KBINS) ? theta[lane] : -__int_as_float(0x7F800000);
        float m = th;
        #pragma unroll
        for (int o = 16; o >= 1; o >>= 1)
            m = fmaxf(m, __shfl_xor_sync(FULL, m, o));
        float e = (lane < KBINS) ? expf(th - m) : 0.0f;
        float sum = e;
        #pragma unroll
        for (int o = 16; o >= 1; o >>= 1)
            sum += __shfl_xor_sync(FULL, sum, o);
        float inv = 1.0f / sum;
        float t = e * inv;                  // theta_tmp[lane]

        // exclusive prefix sum over lanes 0..15 -> beta[lane]
        float beta;
        {
            float ps = t;
            #pragma unroll
            for (int o = 1; o < KBINS; o <<= 1) {
                float u = __shfl_up_sync(FULL, ps, o);
                if (lane >= o) ps += u;
            }
            beta = ps - t;
        }
        float gamma = t * (float)KBINS;

        float s = (float)qp[0];             // Qp (=15)
        float alpha = thr[0];

        if (lane < KBINS) {
            float gx = s * gamma * 0.0625f;
            s_tab[lane] = make_float2(gx, fmaf(-gx, (float)lane, s * beta));
        }

        // expand LUT: lane q finds idx = last j with beta[j] <= q/s
        {
            float tq = (float)lane / s;
            int idx = 0;
            #pragma unroll
            for (int j = 0; j < KBINS; j++) {
                float bj = __shfl_sync(FULL, beta, j);
                if (bj <= tq) idx = j;
            }
            float b_i = __shfl_sync(FULL, beta, idx);
            float g_i = __shfl_sync(FULL, gamma, idx);
            if (lane < KBINS)
                s_lutA[lane] = alpha * ((tq - b_i) / g_i + dst[idx]);
        }
        if (lane == 0) s_c = 16.0f / alpha;
    }
    __syncthreads();

    const float c = s_c;
    const float4* __restrict__ x4 = (const float4*)x;
    float4* __restrict__ o4 = (float4*)out;

    // ---- balanced contiguous tile partition: CTA b owns [first, first+cnt) ----
    int nb = gridDim.x;
    int q = ntiles / nb;
    int r = ntiles - q * nb;
    int b = blockIdx.x;
    int cnt   = q + (b < r ? 1 : 0);
    int first = b * q + (b < r ? b : r);

    for (int k = 0; k < cnt; k++) {
        // Tile: 8 LDG.128 front-batched (MLP=8), compute+store in place.
        int base = (first + k) * TILE4 + (int)threadIdx.x;
        float4 v0 = __ldcs(&x4[base]);
        float4 v1 = __ldcs(&x4[base + TPB]);
        float4 v2 = __ldcs(&x4[base + 2 * TPB]);
        float4 v3 = __ldcs(&x4[base + 3 * TPB]);
        float4 v4 = __ldcs(&x4[base + 4 * TPB]);
        float4 v5 = __ldcs(&x4[base + 5 * TPB]);
        float4 v6 = __ldcs(&x4[base + 6 * TPB]);
        float4 v7 = __ldcs(&x4[base + 7 * TPB]);

        lcq_vec4(v0, c, s_tab, s_lutA);  __stcs(&o4[base],           v0);
        lcq_vec4(v1, c, s_tab, s_lutA);  __stcs(&o4[base + TPB],     v1);
        lcq_vec4(v2, c, s_tab, s_lutA);  __stcs(&o4[base + 2 * TPB], v2);
        lcq_vec4(v3, c, s_tab, s_lutA);  __stcs(&o4[base + 3 * TPB], v3);
        lcq_vec4(v4, c, s_tab, s_lutA);  __stcs(&o4[base + 4 * TPB], v4);
        lcq_vec4(v5, c, s_tab, s_lutA);  __stcs(&o4[base + 5 * TPB], v5);
        lcq_vec4(v6, c, s_tab, s_lutA);  __stcs(&o4[base + 6 * TPB], v6);
        lcq_vec4(v7, c, s_tab, s_lutA);  __stcs(&o4[base + 7 * TPB], v7);
    }

    // ---- remainder (elements beyond the last complete tile) ----
    if (b == nb - 1) {
        for (int i = ntiles * TILE4 + (int)threadIdx.x; i < n4; i += TPB) {
            float4 v = __ldcs(&x4[i]);
            lcq_vec4(v, c, s_tab, s_lutA);
            __stcs(&o4[i], v);
        }
        for (int j = (n4 << 2) + (int)threadIdx.x; j < n; j += TPB) {
            out[j] = lcq_elem(x[j], c, s_tab, s_lutA);
        }
    }
}

extern "C" void kernel_launch(void* const* d_in, const int* in_sizes, int n_in,
                              void* d_out, int out_size) {
    // metadata order: x, threshold, theta, dst, Qn, Qp, num_elements
    const float* x     = (const float*)d_in[0];
    const float* thr   = (const float*)d_in[1];
    const float* theta = (const float*)d_in[2];
    const float* dst   = (const float*)d_in[3];
    const int*   qp    = (const int*)d_in[5];
    float* out = (float*)d_out;

    int n  = in_sizes[0];
    int n4 = n >> 2;
    int ntiles = n4 / TILE4;

    int blocks = 148 * 5;               // persistent: one wave at 5 CTAs/SM
    if (ntiles > 0 && blocks > ntiles) blocks = ntiles;
    if (blocks < 1) blocks = 1;

    lcq_kernel<<<blocks, TPB>>>(x, thr, theta, dst, qp, out, ntiles, n4, n);
}